// round 1
// baseline (speedup 1.0000x reference)
#include <cuda_runtime.h>
#include <math.h>

// ---------------- problem constants ----------------
#define SLOTS      85      // 81 classes + 4 box coords
#define NCLS       81
#define NBINS      4096
#define HIST_LO   (-8.0f)
#define HIST_INVW (256.0f)   // NBINS / (HI-LO) = 4096/16

// ---------------- device scratch (no allocations allowed) ----------------
__device__ int    g_npos;
__device__ double g_pos_loss;
__device__ double g_loc_loss;
__device__ int    g_hist_cnt[NBINS];
__device__ float  g_hist_sum[NBINS];

// ---------------- K0: zero scratch ----------------
__global__ void ssd_init_kernel() {
    int i = blockIdx.x * blockDim.x + threadIdx.x;
    if (i < NBINS) { g_hist_cnt[i] = 0; g_hist_sum[i] = 0.0f; }
    if (i == 0) { g_npos = 0; g_pos_loss = 0.0; g_loc_loss = 0.0; }
}

// ---------------- K1: streaming pass, warp per anchor ----------------
__global__ __launch_bounds__(256) void ssd_main_kernel(
    const float* __restrict__ yp,
    const float* __restrict__ yt,
    int nanch)
{
    __shared__ int   s_cnt[NBINS];
    __shared__ float s_sum[NBINS];
    for (int i = threadIdx.x; i < NBINS; i += blockDim.x) { s_cnt[i] = 0; s_sum[i] = 0.0f; }
    __syncthreads();

    const int lane = threadIdx.x & 31;
    const int warp = threadIdx.x >> 5;
    const int wpb  = blockDim.x >> 5;
    long long wid    = (long long)blockIdx.x * wpb + warp;
    long long stride = (long long)gridDim.x * wpb;

    float accPos = 0.0f, accLoc = 0.0f;
    int   accN = 0;

    for (long long a = wid; a < nanch; a += stride) {
        size_t base = (size_t)a * SLOTS;

        float t0 = yt[base + lane];
        float p0 = yp[base + lane];
        float t1 = yt[base + lane + 32];
        float p1 = yp[base + lane + 32];
        float t2 = 0.0f, p2 = 0.0f;
        if (lane < SLOTS - 64) {               // lane < 21 : idx 64..84
            t2 = yt[base + lane + 64];
            p2 = yp[base + lane + 64];
        }

        // confidence dot over class slots 0..80 (third load is a class slot iff lane<=16)
        float c = t0 * p0 + t1 * p1 + ((lane <= 16) ? t2 * p2 : 0.0f);

        // smooth-L1 on box slots 81..84 (lanes 17..20 of the third load)
        float sl = 0.0f;
        if (lane >= 17 && lane <= 20) {
            float d  = p2 - t2;
            float ad = fabsf(d);
            sl = (ad < 1.0f) ? 0.5f * d * d : (ad - 0.5f);
        }

        // pos: any class slot 1..80 nonzero
        bool pflag = ((lane > 0) && (t0 != 0.0f)) || (t1 != 0.0f) ||
                     ((lane <= 16) && (t2 != 0.0f));
        unsigned pos = __any_sync(0xffffffffu, pflag);

        #pragma unroll
        for (int off = 16; off; off >>= 1) {
            c  += __shfl_down_sync(0xffffffffu, c,  off);
            sl += __shfl_down_sync(0xffffffffu, sl, off);
        }

        if (lane == 0) {
            float conf = -c;
            if (pos) { accN++; accPos += conf; accLoc += sl; }
            if (t0 != 0.0f) {                    // negative (background) anchor
                int bin = (int)((conf - HIST_LO) * HIST_INVW);
                bin = max(0, min(NBINS - 1, bin));
                atomicAdd(&s_cnt[bin], 1);
                atomicAdd(&s_sum[bin], conf);
            }
        }
    }

    if (lane == 0 && accN) {
        atomicAdd(&g_npos, accN);
        atomicAdd(&g_pos_loss, (double)accPos);
        atomicAdd(&g_loc_loss, (double)accLoc);
    }

    __syncthreads();
    for (int i = threadIdx.x; i < NBINS; i += blockDim.x) {
        int cc = s_cnt[i];
        if (cc) {
            atomicAdd(&g_hist_cnt[i], cc);
            atomicAdd(&g_hist_sum[i], s_sum[i]);
        }
    }
}

// ---------------- K2: single-block finalize ----------------
// Histogram bins reordered top-down; suffix-count scan; full bins above the
// threshold bin are summed exactly, the straddling bin contributes
// r * (bin_sum / bin_count).
__global__ __launch_bounds__(1024) void ssd_finalize_kernel(float* __restrict__ out)
{
    __shared__ int    s_cnt[NBINS];
    __shared__ float  s_sumf[NBINS];
    __shared__ int    s_chunk[1024];
    __shared__ double s_neg;

    const int tid = threadIdx.x;
    for (int i = tid; i < NBINS; i += 1024) {
        int b = NBINS - 1 - i;          // i = rank from the top value downward
        s_cnt[i]  = g_hist_cnt[b];
        s_sumf[i] = g_hist_sum[b];
    }
    if (tid == 0) s_neg = 0.0;
    __syncthreads();

    int c0 = s_cnt[tid * 4 + 0];
    int c1 = s_cnt[tid * 4 + 1];
    int c2 = s_cnt[tid * 4 + 2];
    int c3 = s_cnt[tid * 4 + 3];
    int total = c0 + c1 + c2 + c3;

    // inclusive Hillis-Steele scan of per-thread chunk totals
    s_chunk[tid] = total;
    __syncthreads();
    for (int off = 1; off < 1024; off <<= 1) {
        int v = (tid >= off) ? s_chunk[tid - off] : 0;
        __syncthreads();
        s_chunk[tid] += v;
        __syncthreads();
    }
    int cumBefore = s_chunk[tid] - total;   // anchors strictly above this chunk

    int npos = g_npos;
    int nneg = (int)(3.0f * (float)npos);

    double contrib = 0.0;
    int cb = cumBefore;
    int cnts[4] = {c0, c1, c2, c3};
    #pragma unroll
    for (int k = 0; k < 4; k++) {
        int cc = cnts[k];
        if (cc) {
            float s = s_sumf[tid * 4 + k];
            if (cb + cc <= nneg) {
                contrib += (double)s;                                    // fully taken
            } else if (cb < nneg) {
                contrib += (double)s * (double)(nneg - cb) / (double)cc; // partial bin
            }
        }
        cb += cc;
    }
    if (contrib != 0.0) atomicAdd(&s_neg, contrib);
    __syncthreads();

    if (tid == 0) {
        double np = (npos > 0) ? (double)npos : 1.0;
        out[0] = (float)((g_pos_loss + s_neg + g_loc_loss) / np);
    }
}

// ---------------- entry point ----------------
extern "C" void kernel_launch(void* const* d_in, const int* in_sizes, int n_in,
                              void* d_out, int out_size)
{
    const float* y_pred = (const float*)d_in[0];
    const float* y_true = (const float*)d_in[1];
    float* out = (float*)d_out;

    int nanch = in_sizes[0] / SLOTS;

    ssd_init_kernel<<<(NBINS + 255) / 256, 256>>>();
    ssd_main_kernel<<<888, 256>>>(y_pred, y_true, nanch);
    ssd_finalize_kernel<<<1, 1024>>>(out);
}